// round 2
// baseline (speedup 1.0000x reference)
#include <cuda_runtime.h>
#include <math.h>

#define BN   8
#define HH   512
#define WW   1024
#define GG   104857
#define NTOT (BN * GG)          // 838856  (divisible by 4)
#define NQUAD (NTOT / 4)        // 209714
#define HBINS 65536

// ---------------- device scratch (no allocations allowed) ----------------
__device__ float        g_loss[NTOT];
__device__ unsigned int g_hcnt16[HBINS];   // top-16-bit count histogram
__device__ unsigned int g_hcnt_lo[HBINS];  // low-16-bit count histogram (bin-j only)
__device__ float        g_hsum_lo[HBINS];  // low-16-bit sum histogram  (bin-j only)
__device__ double       g_sum_valid;
__device__ double       g_sum_below;       // sum of values with top16 < g_bin
__device__ unsigned int g_n;
__device__ unsigned int g_bin;
__device__ unsigned int g_krem;

// ---------------- init: clear all three histograms + scalars ----------------
__global__ void init_kernel() {
    unsigned int i = blockIdx.x * blockDim.x + threadIdx.x;  // 768*256 = 196608
    if (i < HBINS) {
        g_hcnt16[i] = 0u;
    } else if (i < 2 * HBINS) {
        g_hcnt_lo[i - HBINS] = 0u;
    } else {
        g_hsum_lo[i - 2 * HBINS] = 0.0f;
    }
    if (i == 0) { g_sum_valid = 0.0; g_sum_below = 0.0; }
}

// ---------------- main compute: loss per group + top-16 count hist ----------------
__global__ void __launch_bounds__(256)
compute_kernel(const float* __restrict__ pred,
               const float* __restrict__ tgt,
               const float* __restrict__ intr,
               const int*   __restrict__ p1,
               const int*   __restrict__ p2,
               const int*   __restrict__ p3)
{
    const float EPS   = 1e-6f;
    const float DCOS  = 0.867f;
    const float DDIFF = 0.005f;
    const float DZ    = 1e-5f;
    const float INF_F = __int_as_float(0x7f800000);

    int i = blockIdx.x * blockDim.x + threadIdx.x;
    if (i >= NTOT) return;

    int b = i / GG;
    const float* tb = tgt  + b * (HH * WW);
    const float* pb = pred + b * (HH * WW);
    float f    = __ldg(intr + b * 9 + 0);
    float u0   = __ldg(intr + b * 9 + 2);
    float v0   = __ldg(intr + b * 9 + 5);
    float invf = 1.0f / f;

    int id0 = __ldg(p1 + i);
    int id1 = __ldg(p2 + i);
    int id2 = __ldg(p3 + i);

    // issue all gathers up front for MLP
    float dt0 = __ldg(tb + id0), dt1 = __ldg(tb + id1), dt2 = __ldg(tb + id2);
    float dp0 = __ldg(pb + id0), dp1 = __ldg(pb + id1), dp2 = __ldg(pb + id2);

    float Px[3], Py[3], Pz[3], Qx[3], Qy[3], Qz[3];
    {
        int ids[3] = {id0, id1, id2};
        float dts[3] = {dt0, dt1, dt2};
        float dps[3] = {dp0, dp1, dp2};
        #pragma unroll
        for (int j = 0; j < 3; j++) {
            int id  = ids[j];
            float u = (float)(id & (WW - 1)) - u0;
            float v = (float)(id >> 10)      - v0;
            float dt = dts[j], dp = dps[j];
            Px[j] = u * dt * invf;  Py[j] = v * dt * invf;  Pz[j] = dt;
            Qx[j] = u * dp * invf;  Qy[j] = v * dp * invf;  Qz[j] = dp;
        }
    }

    // GT diffs: D0 = p2-p1, D1 = p3-p1, D2 = p3-p2
    float Dx[3], Dy[3], Dz[3];
    Dx[0] = Px[1] - Px[0]; Dy[0] = Py[1] - Py[0]; Dz[0] = Pz[1] - Pz[0];
    Dx[1] = Px[2] - Px[0]; Dy[1] = Py[2] - Py[0]; Dz[1] = Pz[2] - Pz[0];
    Dx[2] = Px[2] - Px[1]; Dy[2] = Py[2] - Py[1]; Dz[2] = Pz[2] - Pz[1];

    // Gram matrix of diffs (symmetric)
    float e00 = Dx[0]*Dx[0] + Dy[0]*Dy[0] + Dz[0]*Dz[0];
    float e11 = Dx[1]*Dx[1] + Dy[1]*Dy[1] + Dz[1]*Dz[1];
    float e22 = Dx[2]*Dx[2] + Dy[2]*Dy[2] + Dz[2]*Dz[2];
    float e01 = Dx[0]*Dx[1] + Dy[0]*Dy[1] + Dz[0]*Dz[1];
    float e02 = Dx[0]*Dx[2] + Dy[0]*Dy[2] + Dz[0]*Dz[2];
    float e12 = Dx[1]*Dx[2] + Dy[1]*Dy[2] + Dz[1]*Dz[2];

    float qn0 = sqrtf(e00), qn1 = sqrtf(e11), qn2 = sqrtf(e22);

    // |e/(qn_i*qn_j + EPS)| > DCOS  <=>  |e| > DCOS*(qn_i*qn_j + EPS)
    int cnt = 0;
    cnt += (fabsf(e00) > DCOS * (qn0 * qn0 + EPS)) ? 1 : 0;
    cnt += (fabsf(e11) > DCOS * (qn1 * qn1 + EPS)) ? 1 : 0;
    cnt += (fabsf(e22) > DCOS * (qn2 * qn2 + EPS)) ? 1 : 0;
    cnt += (fabsf(e01) > DCOS * (qn0 * qn1 + EPS)) ? 2 : 0;
    cnt += (fabsf(e02) > DCOS * (qn0 * qn2 + EPS)) ? 2 : 0;
    cnt += (fabsf(e12) > DCOS * (qn1 * qn2 + EPS)) ? 2 : 0;
    bool mask_cos = cnt > 3;

    bool mask_pad = (Pz[0] > DZ) && (Pz[1] > DZ) && (Pz[2] > DZ);
    bool mx = (fabsf(Dx[0]) < DDIFF) || (fabsf(Dx[1]) < DDIFF) || (fabsf(Dx[2]) < DDIFF);
    bool my = (fabsf(Dy[0]) < DDIFF) || (fabsf(Dy[1]) < DDIFF) || (fabsf(Dy[2]) < DDIFF);
    bool mz = (fabsf(Dz[0]) < DDIFF) || (fabsf(Dz[1]) < DDIFF) || (fabsf(Dz[2]) < DDIFF);
    bool valid = mask_pad && !((mx && my && mz) || mask_cos);

    // faithful replication of pred_g[pred_g[:,:,2,:]==0] = 1e-4 broadcast quirk:
    // z of point j == 0  =>  coord j of ALL points := 1e-4
    bool c0 = (Qz[0] == 0.0f), c1 = (Qz[1] == 0.0f), c2 = (Qz[2] == 0.0f);
    if (c0) { Qx[0] = 1e-4f; Qx[1] = 1e-4f; Qx[2] = 1e-4f; }
    if (c1) { Qy[0] = 1e-4f; Qy[1] = 1e-4f; Qy[2] = 1e-4f; }
    if (c2) { Qz[0] = 1e-4f; Qz[1] = 1e-4f; Qz[2] = 1e-4f; }

    // GT normal: cross(D0, D1)
    float ngx = Dy[0] * Dz[1] - Dz[0] * Dy[1];
    float ngy = Dz[0] * Dx[1] - Dx[0] * Dz[1];
    float ngz = Dx[0] * Dy[1] - Dy[0] * Dx[1];
    float nng = sqrtf(ngx * ngx + ngy * ngy + ngz * ngz);
    if (nng == 0.0f) nng = EPS;
    float ig = 1.0f / nng;
    ngx *= ig; ngy *= ig; ngz *= ig;

    // pred normal
    float ax = Qx[1] - Qx[0], ay = Qy[1] - Qy[0], az = Qz[1] - Qz[0];
    float bx = Qx[2] - Qx[0], by = Qy[2] - Qy[0], bz = Qz[2] - Qz[0];
    float npx = ay * bz - az * by;
    float npy = az * bx - ax * bz;
    float npz = ax * by - ay * bx;
    float nnp = sqrtf(npx * npx + npy * npy + npz * npz);
    if (nnp == 0.0f) nnp = EPS;
    float ip = 1.0f / nnp;
    npx *= ip; npy *= ip; npz *= ip;

    float loss = fabsf(ngx - npx) + fabsf(ngy - npy) + fabsf(ngz - npz);

    float out = valid ? loss : INF_F;   // +inf sinks past all finite values
    g_loss[i] = out;
    atomicAdd(&g_hcnt16[__float_as_uint(out) >> 16], 1u);  // RED, no return
}

// ---------------- resolve top-16: find bin holding the k-th smallest ----------------
__global__ void resolve16_kernel()
{
    __shared__ unsigned int ccnt[256];
    int t = threadIdx.x;
    unsigned int c = 0;
    int base = t << 8;
    #pragma unroll 8
    for (int j = 0; j < 256; j++) c += g_hcnt16[base + j];
    ccnt[t] = c;
    __syncthreads();

    if (t == 0) {
        unsigned int n = NTOT - g_hcnt16[0x7f80];  // finite (= valid) count
        unsigned int k = n >> 2;                   // drop n//4 smallest
        g_n = n;

        unsigned int cum = 0; int chunk = 0;
        for (int ch = 0; ch < 256; ch++) {
            if (cum + ccnt[ch] >= k) { chunk = ch; break; }
            cum += ccnt[ch];
        }
        unsigned int bin = (unsigned int)(chunk << 8), krem = 0;
        for (int j = chunk << 8; ; j++) {
            unsigned int cj = g_hcnt16[j];
            if (cum + cj >= k) { bin = (unsigned int)j; krem = k - cum; break; }
            cum += cj;
        }
        g_bin  = bin;
        g_krem = krem;
    }
}

// ---------------- passB: Σ_valid, Σ(top16<bin), low-16 hist of bin-j values ----------------
__global__ void __launch_bounds__(256)
passB_kernel()
{
    __shared__ float sh_v[8], sh_b[8];

    unsigned int j = g_bin;
    float sv = 0.0f, sb = 0.0f;

    int q = blockIdx.x * blockDim.x + threadIdx.x;
    if (q < NQUAD) {
        float4 v4 = reinterpret_cast<const float4*>(g_loss)[q];
        float vs[4] = {v4.x, v4.y, v4.z, v4.w};
        #pragma unroll
        for (int e = 0; e < 4; e++) {
            float v = vs[e];
            unsigned int bits = __float_as_uint(v);
            if (bits < 0x7f800000u) sv += v;       // finite = valid
            unsigned int top = bits >> 16;
            if (top < j) {
                sb += v;
            } else if (top == j) {
                atomicAdd(&g_hcnt_lo[bits & 0xffffu], 1u);
                atomicAdd(&g_hsum_lo[bits & 0xffffu], v);
            }
        }
    }

    #pragma unroll
    for (int o = 16; o > 0; o >>= 1) {
        sv += __shfl_down_sync(0xffffffffu, sv, o);
        sb += __shfl_down_sync(0xffffffffu, sb, o);
    }
    int wid = threadIdx.x >> 5, lid = threadIdx.x & 31;
    if (lid == 0) { sh_v[wid] = sv; sh_b[wid] = sb; }
    __syncthreads();
    if (threadIdx.x == 0) {
        float tv = 0.0f, tb = 0.0f;
        #pragma unroll
        for (int w = 0; w < 8; w++) { tv += sh_v[w]; tb += sh_b[w]; }
        atomicAdd(&g_sum_valid, (double)tv);
        atomicAdd(&g_sum_below, (double)tb);
    }
}

// ---------------- resolve low-16 + assemble final scalar ----------------
__global__ void finish_kernel(float* __restrict__ out)
{
    __shared__ unsigned int ccnt[256];
    int t = threadIdx.x;
    unsigned int c = 0;
    int base = t << 8;
    #pragma unroll 8
    for (int j = 0; j < 256; j++) c += g_hcnt_lo[base + j];
    ccnt[t] = c;
    __syncthreads();

    if (t == 0) {
        unsigned int krem = g_krem;

        unsigned int cum = 0; int chunk = 0;
        for (int ch = 0; ch < 256; ch++) {
            if (cum + ccnt[ch] >= krem) { chunk = ch; break; }
            cum += ccnt[ch];
        }
        // rescan fine bins of the chunk, accumulating exact sum below
        double sum_lo_below = 0.0;
        // sum of hsum_lo over full chunks below `chunk`
        for (int ch = 0; ch < chunk; ch++) {
            // ccnt only has counts; need sums: walk those chunks' sums
            // (256*chunk loads worst case 64K — but chunk is found early in
            //  practice; bound is acceptable for a 1-block epilogue)
            ;
        }
        // accumulate sums for all bins below the selected fine bin
        unsigned int cum2 = 0; unsigned int lobin = (unsigned int)(chunk << 8);
        // first add sums of all full chunks below
        double sum_full = 0.0;
        for (int ch = 0; ch < chunk; ch++) {
            int b0 = ch << 8;
            float s = 0.0f;
            for (int j = 0; j < 256; j++) s += g_hsum_lo[b0 + j];
            sum_full += (double)s;
        }
        cum2 = cum;  // counts below chunk already accumulated
        for (int j = chunk << 8; ; j++) {
            unsigned int cj = g_hcnt_lo[j];
            if (cum2 + cj >= krem) { lobin = (unsigned int)j; break; }
            cum2 += cj;
            sum_lo_below += (double)g_hsum_lo[j];
        }
        float tf = __uint_as_float((g_bin << 16) | lobin);
        double sum_small = g_sum_below + sum_full + sum_lo_below
                         + (double)(krem - cum2) * (double)tf;
        unsigned int n = g_n;
        long long d = (long long)n - (long long)(n >> 2);
        if (d < 1) d = 1;
        out[0] = (float)((g_sum_valid - sum_small) / (double)d);
    }
}

// ---------------- launch ----------------
extern "C" void kernel_launch(void* const* d_in, const int* in_sizes, int n_in,
                              void* d_out, int out_size)
{
    const float* pred = (const float*)d_in[0];
    const float* tgt  = (const float*)d_in[1];
    // d_in[2] = mask (already baked into p1/p2/p3; unused)
    const float* intr = (const float*)d_in[3];
    const int*   p1   = (const int*)d_in[4];
    const int*   p2   = (const int*)d_in[5];
    const int*   p3   = (const int*)d_in[6];
    float* out = (float*)d_out;

    init_kernel<<<768, 256>>>();                       // 196608 = 3*65536 words
    compute_kernel<<<(NTOT + 255) / 256, 256>>>(pred, tgt, intr, p1, p2, p3);
    resolve16_kernel<<<1, 256>>>();
    passB_kernel<<<(NQUAD + 255) / 256, 256>>>();
    finish_kernel<<<1, 256>>>(out);
}